// round 3
// baseline (speedup 1.0000x reference)
#include <cuda_runtime.h>
#include <math.h>

#define BB 32
#define HH 32
#define KVHH 8
#define DD 128
#define GG 4
#define BLK_SZ 16
#define MAX_BLOCKS 128
#define NSPLIT 8
#define NWARP 8
#define NTHREADS 256

typedef unsigned long long u64;

// Scratch (allocation-free: __device__ globals)
__device__ float g_pacc[BB * KVHH * NSPLIT * GG * DD];  // 4 MB split partials
__device__ float g_pm[BB * KVHH * NSPLIT * GG];
__device__ float g_pl[BB * KVHH * NSPLIT * GG];
__device__ float g_qrot[BB * HH * DD];    // RoPE'd q, scale folded
__device__ float g_krot[BB * KVHH * DD];  // RoPE'd new k

// ---------- packed f32x2 helpers (sm_103a) ----------
__device__ __forceinline__ u64 pack2(float lo, float hi) {
    u64 r; asm("mov.b64 %0,{%1,%2};" : "=l"(r) : "f"(lo), "f"(hi)); return r;
}
__device__ __forceinline__ u64 dup2(float v) { return pack2(v, v); }
__device__ __forceinline__ float2 unpk(u64 v) {
    float2 r; asm("mov.b64 {%0,%1},%2;" : "=f"(r.x), "=f"(r.y) : "l"(v)); return r;
}
__device__ __forceinline__ u64 fma2(u64 a, u64 b, u64 c) {
    u64 d; asm("fma.rn.f32x2 %0,%1,%2,%3;" : "=l"(d) : "l"(a), "l"(b), "l"(c)); return d;
}
__device__ __forceinline__ u64 mul2(u64 a, u64 b) {
    u64 d; asm("mul.rn.f32x2 %0,%1,%2;" : "=l"(d) : "l"(a), "l"(b)); return d;
}

// ---------------- prep: RoPE q and new-k once ----------------
__global__ __launch_bounds__(DD) void rope_prep_kernel(
    const float* __restrict__ query,
    const float* __restrict__ key,
    const int*   __restrict__ context_lens)
{
    const int b = blockIdx.x;
    const int h = blockIdx.y;   // 0..HH-1 q head, HH..HH+KVHH-1 k head
    const int d = threadIdx.x;

    const float pos = (float)context_lens[b];
    const int fi = d & 63;
    const float inv = exp2f(-(float)fi * 0.2076205092783674f);
    float s, c;
    sincosf(pos * inv, &s, &c);

    if (h < HH) {
        const float* base = query + ((long)b * HH + h) * DD;
        float x = base[d];
        float other = (d < 64) ? -base[d + 64] : base[d - 64];
        g_qrot[((long)b * HH + h) * DD + d] =
            (x * c + other * s) * 0.08838834764831845f;
    } else {
        const int kh = h - HH;
        const float* base = key + ((long)b * KVHH + kh) * DD;
        float x = base[d];
        float other = (d < 64) ? -base[d + 64] : base[d - 64];
        g_krot[((long)b * KVHH + kh) * DD + d] = x * c + other * s;
    }
}

// ---------- distributed 4-head dot: lane owns dims 4*lane..4*lane+3 ----------
__device__ __forceinline__ void dotg(ulonglong2 kv, const u64 q[GG][2], float sc[GG]) {
#pragma unroll
    for (int g = 0; g < GG; g++) {
        u64 t = fma2(kv.y, q[g][1], mul2(kv.x, q[g][0]));
        float2 f = unpk(t);
        sc[g] = f.x + f.y;
    }
}

// ---------- 7-SHFL multi-value fold: returns full score of head (lane&3) ----------
__device__ __forceinline__ float fold4(float s0, float s1, float s2, float s3, int lane) {
    bool b0 = lane & 1;
    float a01 = b0 ? s1 : s0, o01 = b0 ? s0 : s1;
    a01 += __shfl_xor_sync(0xffffffffu, o01, 1);
    float a23 = b0 ? s3 : s2, o23 = b0 ? s2 : s3;
    a23 += __shfl_xor_sync(0xffffffffu, o23, 1);
    bool b1 = lane & 2;
    float v = b1 ? a23 : a01, o = b1 ? a01 : a23;
    v += __shfl_xor_sync(0xffffffffu, o, 2);
    v += __shfl_xor_sync(0xffffffffu, v, 4);
    v += __shfl_xor_sync(0xffffffffu, v, 8);
    v += __shfl_xor_sync(0xffffffffu, v, 16);
    return v;
}

// ---------- 4-token softmax/accumulate group (one rescale per 4 tokens) ----------
__device__ __forceinline__ void group4(
    float s0, float s1, float s2, float s3,
    ulonglong2 v0, ulonglong2 v1, ulonglong2 v2, ulonglong2 v3,
    float& m_own, float& l_own, u64 acc[GG][2])
{
    float smax = fmaxf(fmaxf(s0, s1), fmaxf(s2, s3));
    float mn = fmaxf(m_own, smax);
    float alpha = __expf(m_own - mn);
    m_own = mn;
    float p0 = __expf(s0 - mn), p1 = __expf(s1 - mn);
    float p2 = __expf(s2 - mn), p3 = __expf(s3 - mn);
    l_own = l_own * alpha + ((p0 + p1) + (p2 + p3));
#pragma unroll
    for (int g = 0; g < GG; g++) {
        u64 ag = dup2(__shfl_sync(0xffffffffu, alpha, g));
        acc[g][0] = mul2(acc[g][0], ag);
        acc[g][1] = mul2(acc[g][1], ag);
    }
#pragma unroll
    for (int g = 0; g < GG; g++) {
        u64 pg = dup2(__shfl_sync(0xffffffffu, p0, g));
        acc[g][0] = fma2(pg, v0.x, acc[g][0]);
        acc[g][1] = fma2(pg, v0.y, acc[g][1]);
    }
#pragma unroll
    for (int g = 0; g < GG; g++) {
        u64 pg = dup2(__shfl_sync(0xffffffffu, p1, g));
        acc[g][0] = fma2(pg, v1.x, acc[g][0]);
        acc[g][1] = fma2(pg, v1.y, acc[g][1]);
    }
#pragma unroll
    for (int g = 0; g < GG; g++) {
        u64 pg = dup2(__shfl_sync(0xffffffffu, p2, g));
        acc[g][0] = fma2(pg, v2.x, acc[g][0]);
        acc[g][1] = fma2(pg, v2.y, acc[g][1]);
    }
#pragma unroll
    for (int g = 0; g < GG; g++) {
        u64 pg = dup2(__shfl_sync(0xffffffffu, p3, g));
        acc[g][0] = fma2(pg, v3.x, acc[g][0]);
        acc[g][1] = fma2(pg, v3.y, acc[g][1]);
    }
}

__device__ __forceinline__ void one_token(
    ulonglong2 kq, ulonglong2 vq, const u64 q[GG][2],
    float& m_own, float& l_own, u64 acc[GG][2], int lane)
{
    float sc[GG];
    dotg(kq, q, sc);
    float s = fold4(sc[0], sc[1], sc[2], sc[3], lane);
    float mn = fmaxf(m_own, s);
    float alpha = __expf(m_own - mn);
    float p = __expf(s - mn);
    m_own = mn;
    l_own = l_own * alpha + p;
#pragma unroll
    for (int g = 0; g < GG; g++) {
        u64 ag = dup2(__shfl_sync(0xffffffffu, alpha, g));
        u64 pg = dup2(__shfl_sync(0xffffffffu, p, g));
        acc[g][0] = fma2(pg, vq.x, mul2(acc[g][0], ag));
        acc[g][1] = fma2(pg, vq.y, mul2(acc[g][1], ag));
    }
}

// ---------------- split flash-decode ----------------
__global__ __launch_bounds__(NTHREADS) void pa_split_kernel(
    const float* __restrict__ value,
    const float* __restrict__ k_cache,
    const float* __restrict__ v_cache,
    const int*   __restrict__ block_table,
    const int*   __restrict__ context_lens)
{
    const int split = blockIdx.x;
    const int kvh   = blockIdx.y;
    const int b     = blockIdx.z;
    const int tid   = threadIdx.x;
    const int lane  = tid & 31;
    const int w     = tid >> 5;

    const int ctx   = context_lens[b];
    const int chunk = (ctx + NSPLIT - 1) / NSPLIT;
    const int s0    = split * chunk;
    const int s1    = min(s0 + chunk, ctx);
    const int last  = ctx - 1;
    const int end   = min(s1, last);   // hot loop excludes in-flight token

    __shared__ int   btab[MAX_BLOCKS];
    __shared__ float wm[NWARP][GG];
    __shared__ float wl[NWARP][GG];
    __shared__ float wacc[NWARP][GG][DD];
    __shared__ float ff[NWARP][GG];
    __shared__ float fM[GG], fL[GG];

    for (int i = tid; i < MAX_BLOCKS; i += NTHREADS)
        btab[i] = block_table[b * MAX_BLOCKS + i];
    __syncthreads();

    u64 q[GG][2];
#pragma unroll
    for (int g = 0; g < GG; g++) {
        const ulonglong2 qq = *(const ulonglong2*)
            &g_qrot[((long)b * HH + kvh * GG + g) * DD + lane * 4];
        q[g][0] = qq.x; q[g][1] = qq.y;
    }

    float m_own = -1e30f, l_own = 0.f;
    u64 acc[GG][2];
#pragma unroll
    for (int g = 0; g < GG; g++) { acc[g][0] = 0ull; acc[g][1] = 0ull; }

    const unsigned hoff = (unsigned)kvh * DD + lane * 4;

    int s = s0 + w;
    while (s + 3 * NWARP < end) {
        unsigned o0, o1, o2, o3;
        {
            int t0 = s, t1 = s + NWARP, t2 = s + 2 * NWARP, t3 = s + 3 * NWARP;
            o0 = (((unsigned)btab[t0 >> 4] * BLK_SZ + (t0 & 15)) * (KVHH * DD)) + hoff;
            o1 = (((unsigned)btab[t1 >> 4] * BLK_SZ + (t1 & 15)) * (KVHH * DD)) + hoff;
            o2 = (((unsigned)btab[t2 >> 4] * BLK_SZ + (t2 & 15)) * (KVHH * DD)) + hoff;
            o3 = (((unsigned)btab[t3 >> 4] * BLK_SZ + (t3 & 15)) * (KVHH * DD)) + hoff;
        }
        ulonglong2 k0 = *(const ulonglong2*)(k_cache + o0);
        ulonglong2 v0 = *(const ulonglong2*)(v_cache + o0);
        ulonglong2 k1 = *(const ulonglong2*)(k_cache + o1);
        ulonglong2 v1 = *(const ulonglong2*)(v_cache + o1);
        ulonglong2 k2 = *(const ulonglong2*)(k_cache + o2);
        ulonglong2 v2 = *(const ulonglong2*)(v_cache + o2);
        ulonglong2 k3 = *(const ulonglong2*)(k_cache + o3);
        ulonglong2 v3 = *(const ulonglong2*)(v_cache + o3);

        float a0[GG], a1[GG], a2[GG], a3[GG];
        dotg(k0, q, a0); dotg(k1, q, a1); dotg(k2, q, a2); dotg(k3, q, a3);
        float s0f = fold4(a0[0], a0[1], a0[2], a0[3], lane);
        float s1f = fold4(a1[0], a1[1], a1[2], a1[3], lane);
        float s2f = fold4(a2[0], a2[1], a2[2], a2[3], lane);
        float s3f = fold4(a3[0], a3[1], a3[2], a3[3], lane);
        group4(s0f, s1f, s2f, s3f, v0, v1, v2, v3, m_own, l_own, acc);
        s += 4 * NWARP;
    }
    while (s < end) {
        unsigned off = (((unsigned)btab[s >> 4] * BLK_SZ + (s & 15)) * (KVHH * DD)) + hoff;
        ulonglong2 kq = *(const ulonglong2*)(k_cache + off);
        ulonglong2 vq = *(const ulonglong2*)(v_cache + off);
        one_token(kq, vq, q, m_own, l_own, acc, lane);
        s += NWARP;
    }

    // in-flight token (RoPE'd new k from scratch, new v from input)
    if (last >= s0 && last < s1 && w == ((last - s0) % NWARP)) {
        ulonglong2 kq = *(const ulonglong2*)
            &g_krot[((long)b * KVHH + kvh) * DD + lane * 4];
        ulonglong2 vq = *(const ulonglong2*)
            (value + ((long)b * KVHH + kvh) * DD + lane * 4);
        one_token(kq, vq, q, m_own, l_own, acc, lane);
    }

    // stash per-warp partials (m/l replicated across 8 lane-groups; lanes 0..3 = g)
    if (lane < GG) { wm[w][lane] = m_own; wl[w][lane] = l_own; }
#pragma unroll
    for (int g = 0; g < GG; g++) {
        float2 a = unpk(acc[g][0]);
        float2 c = unpk(acc[g][1]);
        float4 o; o.x = a.x; o.y = a.y; o.z = c.x; o.w = c.y;
        *(float4*)&wacc[w][g][lane * 4] = o;
    }
    __syncthreads();

    if (tid < GG) {
        int g = tid;
        float M = -1e30f;
#pragma unroll
        for (int ww = 0; ww < NWARP; ww++) M = fmaxf(M, wm[ww][g]);
        float L = 0.f;
#pragma unroll
        for (int ww = 0; ww < NWARP; ww++) {
            float f = __expf(wm[ww][g] - M);
            ff[ww][g] = f;
            L += f * wl[ww][g];
        }
        fM[g] = M; fL[g] = L;
    }
    __syncthreads();

    const long pbase = ((long)(b * KVHH + kvh) * NSPLIT + split) * GG;
    for (int i = tid; i < GG * DD; i += NTHREADS) {
        int g = i >> 7, d = i & 127;
        float t = 0.f;
#pragma unroll
        for (int ww = 0; ww < NWARP; ww++) t += ff[ww][g] * wacc[ww][g][d];
        g_pacc[(pbase + g) * DD + d] = t;
    }
    if (tid < GG) {
        g_pm[pbase + tid] = fM[tid];
        g_pl[pbase + tid] = fL[tid];
    }
}

// ---------------- combine ----------------
__global__ __launch_bounds__(DD) void pa_combine_kernel(float* __restrict__ out) {
    const int idx = blockIdx.x;             // B*KVH*G
    const int g   = idx % GG;
    const int kvh = (idx / GG) % KVHH;
    const int b   = idx / (GG * KVHH);
    const int d   = threadIdx.x;

    const long base = ((long)(b * KVHH + kvh) * NSPLIT) * GG + g;
    float M = -1e30f;
#pragma unroll
    for (int s = 0; s < NSPLIT; s++) M = fmaxf(M, g_pm[base + (long)s * GG]);
    float L = 0.f, o = 0.f;
#pragma unroll
    for (int s = 0; s < NSPLIT; s++) {
        float f = __expf(g_pm[base + (long)s * GG] - M);
        L += f * g_pl[base + (long)s * GG];
        o += f * g_pacc[(base + (long)s * GG) * DD + d];
    }
    out[((long)b * HH + kvh * GG + g) * DD + d] = o / L;
}

extern "C" void kernel_launch(void* const* d_in, const int* in_sizes, int n_in,
                              void* d_out, int out_size) {
    const float* query  = (const float*)d_in[0];
    const float* key    = (const float*)d_in[1];
    const float* value  = (const float*)d_in[2];
    const float* k_cache = (const float*)d_in[3];
    const float* v_cache = (const float*)d_in[4];
    const int*   block_table  = (const int*)d_in[5];
    const int*   context_lens = (const int*)d_in[6];
    float* out = (float*)d_out;

    dim3 pgrid(BB, HH + KVHH);
    rope_prep_kernel<<<pgrid, DD>>>(query, key, context_lens);

    dim3 grid(NSPLIT, KVHH, BB);
    pa_split_kernel<<<grid, NTHREADS>>>(value, k_cache, v_cache,
                                        block_table, context_lens);
    pa_combine_kernel<<<BB * KVHH * GG, DD>>>(out);
}